// round 13
// baseline (speedup 1.0000x reference)
#include <cuda_runtime.h>
#include <cstdint>

#define NB     64
#define NT     100
#define NA     8732
#define TPB    256
#define NBLK   ((NA + TPB - 1) / TPB)   // 35 anchor tiles
#define NITEM  (NBLK * NB)              // 2240 work items
#define GRIDM  1184                     // 8 blocks/SM * 148 SMs = one full wave

// Scratch (static __device__ — allocation is forbidden). Everything here is
// fully (over)written each replay before being read — no init kernel needed.
__device__ float              g_gt_ov [NB * NA];
__device__ int                g_gt_idx[NB * NA];
__device__ unsigned long long g_part  [NBLK * NB * NT];  // per (tile,b,t) best key
__device__ int                g_ovr   [NB * NA];         // override target id, -1 = none

// key = (iou_bits << 32) | (0xFFFFFFFF - anchor).  iou >= 0 so float bits are
// order-preserving; low word makes ties resolve to the LOWEST anchor index
// (jnp.argmax semantics). max over keys is associative -> deterministic merge.

// Exactly-rounded f32 division, fast path only (no FCHK / no branch).
// Valid: denom is normal & in [4e-4, 2.4], inter in [0, 1.2] — identical
// result sequence to ptxas's div.rn.f32 fast path.
__device__ __forceinline__ float fdiv_rn_fast(float x, float d) {
    float y0;
    asm("rcp.approx.f32 %0, %1;" : "=f"(y0) : "f"(d));
    const float e  = __fmaf_rn(-d, y0, 1.0f);
    const float y1 = __fmaf_rn(y0, e, y0);
    const float q0 = __fmul_rn(x, y1);
    const float r  = __fmaf_rn(-d, q0, x);
    return __fmaf_rn(r, y1, q0);
}

__device__ __forceinline__ unsigned long long pack2(float lo, float hi) {
    unsigned long long r;
    asm("mov.b64 %0, {%1, %2};" : "=l"(r) : "f"(lo), "f"(hi));
    return r;
}

// -------------------------------------------------------------------------
// Kernel 1: IoU pass, persistent-even distribution. grid = 1184 blocks,
//   each loops items (tile,b) with stride gridDim.x — one full wave, no
//   half-empty second wave. Inner t-loop identical to R12 (proven floor).
// -------------------------------------------------------------------------
__global__ __launch_bounds__(TPB) void k_main(const float* __restrict__ targets,
                                              const float* __restrict__ anchors) {
    __shared__ float4             s_box [NT];
    __shared__ float              s_area[NT];
    __shared__ unsigned long long s_key [8 * NT];   // [warp][t]

    const int tid  = threadIdx.x;
    const int wid  = tid >> 5;
    const int lane = tid & 31;

    const unsigned long long neg1 = pack2(-1.0f, -1.0f);
    unsigned long long* skw = &s_key[wid * NT];

    for (int item = blockIdx.x; item < NITEM; item += GRIDM) {
        const int b    = item / NBLK;
        const int tile = item - b * NBLK;

        __syncthreads();   // protect smem from previous item's readers
        for (int t = tid; t < NT; t += TPB) {
            const float* tp = targets + ((size_t)b * NT + t) * 5;
            float x1 = tp[0], y1 = tp[1], x2 = tp[2], y2 = tp[3];
            s_box[t]  = make_float4(x1, y1, x2, y2);
            s_area[t] = __fmul_rn(__fsub_rn(x2, x1), __fsub_rn(y2, y1));
        }
        // REQUIRED: fully-OOB warps never store keys; their slots must be 0.
        for (int i = tid; i < 8 * NT; i += TPB) s_key[i] = 0ull;
        __syncthreads();

        const int  a       = tile * TPB + tid;
        const bool valid   = (a < NA);
        const int  a_ld    = valid ? a : (NA - 1);   // OOB lanes dup last anchor
        const int  warp_a0 = tile * TPB + wid * 32;
        const bool w_store = (lane == 0) && (warp_a0 < NA);
        // REAL a (not clamped): OOB lanes get strictly smaller inv than the
        // valid lane holding the same iou — they can never win the election.
        const unsigned inv_a = 0xFFFFFFFFu - (unsigned)a;

        // anchor point-form, replicating reference arithmetic exactly
        const float4 an = reinterpret_cast<const float4*>(anchors)[a_ld];
        const float hw  = __fmul_rn(an.z, 0.5f);
        const float hh  = __fmul_rn(an.w, 0.5f);
        const float ax1 = __fsub_rn(an.x, hw), ay1 = __fsub_rn(an.y, hh);
        const float ax2 = __fadd_rn(an.x, hw), ay2 = __fadd_rn(an.y, hh);
        const float areaA = __fmul_rn(__fsub_rn(ax2, ax1), __fsub_rn(ay2, ay1));

        float best_ov = -1.0f;
        int   best_t  = 0;

#pragma unroll 10
        for (int t = 0; t < NT; ++t) {
            const float4 tb   = s_box[t];
            const float areaB = s_area[t];
            const float tlx = fmaxf(tb.x, ax1);
            const float tly = fmaxf(tb.y, ay1);
            const float brx = fminf(tb.z, ax2);
            const float bry = fminf(tb.w, ay2);

            // d = br - tl for both components in ONE packed fma (tl*(-1)+br),
            // exactly-rounded rn subtract per lane (== __fsub_rn).
            unsigned long long tl2 = pack2(tlx, tly);
            unsigned long long br2 = pack2(brx, bry);
            unsigned long long d2;
            asm("fma.rn.f32x2 %0, %1, %2, %3;"
                : "=l"(d2) : "l"(tl2), "l"(neg1), "l"(br2));
            float dxr, dyr;
            asm("mov.b64 {%0, %1}, %2;" : "=f"(dxr), "=f"(dyr) : "l"(d2));

            const float dx  = fmaxf(dxr, 0.0f);
            const float dy  = fmaxf(dyr, 0.0f);
            const float inter = __fmul_rn(dx, dy);
            const float denom = __fsub_rn(__fadd_rn(areaB, areaA), inter);
            const float iou   = fdiv_rn_fast(inter, denom);

            // per-anchor argmax over t (strict > keeps first/lowest t)
            const bool gt = (iou > best_ov);
            best_ov = gt ? iou : best_ov;
            best_t  = gt ? t   : best_t;

            // per-target warp argmax: double REDUX (uniform), lane-0 store
            const unsigned ib   = __float_as_uint(iou);
            const unsigned wmax = __reduce_max_sync(0xFFFFFFFFu, ib);
            const unsigned cand = (ib == wmax) ? inv_a : 0u;
            const unsigned wlow = __reduce_max_sync(0xFFFFFFFFu, cand);
            if (w_store)
                skw[t] = ((unsigned long long)wmax << 32) |
                         (unsigned long long)wlow;
        }

        if (valid) {
            g_gt_ov [(size_t)b * NA + a] = best_ov;
            g_gt_idx[(size_t)b * NA + a] = best_t;
            g_ovr   [(size_t)b * NA + a] = -1;        // cleared for k_merge
        }

        __syncthreads();
        // merge 8 warps -> one key per t for this anchor tile
        if (tid < NT) {
            unsigned long long m = 0ull;
#pragma unroll
            for (int w = 0; w < 8; ++w) {
                unsigned long long v = s_key[w * NT + tid];
                m = (v > m) ? v : m;
            }
            g_part[((size_t)tile * NB + b) * NT + tid] = m;
        }
    }
}

// -------------------------------------------------------------------------
// Kernel 2: merge tiles + scatter override. 6400 threads, one per (b,t).
//   Last-t-wins scatter via atomicMax on t (== in-order scatter semantics).
// -------------------------------------------------------------------------
__global__ __launch_bounds__(TPB) void k_merge() {
    const int i = blockIdx.x * TPB + threadIdx.x;
    if (i >= NB * NT) return;
    const int b = i / NT;
    const int t = i - b * NT;

    unsigned long long m = 0ull;
#pragma unroll
    for (int p = 0; p < NBLK; ++p) {
        unsigned long long v = g_part[((size_t)p * NB + b) * NT + t];
        m = (v > m) ? v : m;
    }
    const int aidx = (int)(0xFFFFFFFFu - (unsigned)(m & 0xFFFFFFFFull));
    atomicMax(&g_ovr[(size_t)b * NA + aidx], t);
}

// -------------------------------------------------------------------------
// Kernel 3: finalize / encode. grid = (NBLK, NB), block = 256.
//   Output-only math: fast log/div are fine (1e-6 err vs 1e-3 tolerance);
//   all argmax/threshold-relevant values came from the exact pass.
// -------------------------------------------------------------------------
__global__ __launch_bounds__(TPB) void k_final(const float* __restrict__ targets,
                                               const float* __restrict__ anchors,
                                               float* __restrict__ out) {
    __shared__ float4 s_box[NT];
    __shared__ float  s_lab[NT];

    const int tid = threadIdx.x;
    const int b   = blockIdx.y;

    for (int t = tid; t < NT; t += TPB) {
        const float* tp = targets + ((size_t)b * NT + t) * 5;
        s_box[t] = make_float4(tp[0], tp[1], tp[2], tp[3]);
        s_lab[t] = tp[4];
    }
    __syncthreads();

    const int a = blockIdx.x * TPB + tid;
    if (a >= NA) return;

    int   gi = g_gt_idx[(size_t)b * NA + a];
    float ov = g_gt_ov [(size_t)b * NA + a];
    const int ovr = g_ovr[(size_t)b * NA + a];
    if (ovr >= 0) { gi = ovr; ov = 1.0f; }

    const float4 m   = s_box[gi];
    const float  lab = s_lab[gi];
    const float4 an  = reinterpret_cast<const float4*>(anchors)[a];

    const float cx = (m.x + m.z) * 0.5f;
    const float cy = (m.y + m.w) * 0.5f;
    const float w  = m.z - m.x;
    const float h  = m.w - m.y;

    const float lx = __fdividef(cx - an.x, 0.1f * an.z);
    const float ly = __fdividef(cy - an.y, 0.1f * an.w);
    const float lw = __logf(__fdividef(w, an.z)) * 5.0f;
    const float lh = __logf(__fdividef(h, an.w)) * 5.0f;

    const size_t base = (size_t)b * NA + a;
    reinterpret_cast<float4*>(out)[base] = make_float4(lx, ly, lw, lh);

    const float conf = (ov < 0.5f) ? 0.0f : (lab + 1.0f);
    out[(size_t)NB * NA * 4 + base] = conf;
}

// -------------------------------------------------------------------------
extern "C" void kernel_launch(void* const* d_in, const int* in_sizes, int n_in,
                              void* d_out, int out_size) {
    const float* targets = (const float*)d_in[0];   // [B, T, 5]
    const float* anchors = (const float*)d_in[1];   // [A, 4]
    float* out = (float*)d_out;                     // [B*A*4 loc][B*A conf]

    k_main <<<GRIDM, TPB>>>(targets, anchors);
    k_merge<<<(NB * NT + TPB - 1) / TPB, TPB>>>();
    k_final<<<dim3(NBLK, NB), TPB>>>(targets, anchors, out);
}

// round 16
// speedup vs baseline: 1.8921x; 1.8921x over previous
#include <cuda_runtime.h>
#include <cstdint>

#define NB   64
#define NT   100
#define NA   8732
#define TPB  256
#define NBLK ((NA + TPB - 1) / TPB)   // 35 anchor tiles

// Scratch (static __device__ — allocation is forbidden). Everything here is
// fully (over)written each replay before being read — no init kernel needed.
__device__ float              g_gt_ov [NB * NA];
__device__ int                g_gt_idx[NB * NA];
__device__ unsigned long long g_part  [NBLK * NB * NT];  // per (tile,b,t) best key
__device__ int                g_ovr   [NB * NA];         // override target id, -1 = none

// key = (iou_bits << 32) | (0xFFFFFFFF - anchor).  iou >= 0 so float bits are
// order-preserving; low word makes ties resolve to the LOWEST anchor index
// (jnp.argmax semantics). max over keys is associative -> deterministic merge.

// Exactly-rounded f32 division, fast path only (no FCHK / no branch).
// Valid: denom is normal & in [4e-4, 2.4], inter in [0, 1.2] — identical
// result sequence to ptxas's div.rn.f32 fast path.
__device__ __forceinline__ float fdiv_rn_fast(float x, float d) {
    float y0;
    asm("rcp.approx.f32 %0, %1;" : "=f"(y0) : "f"(d));
    const float e  = __fmaf_rn(-d, y0, 1.0f);
    const float y1 = __fmaf_rn(y0, e, y0);
    const float q0 = __fmul_rn(x, y1);
    const float r  = __fmaf_rn(-d, q0, x);
    return __fmaf_rn(r, y1, q0);
}

__device__ __forceinline__ unsigned long long pack2(float lo, float hi) {
    unsigned long long r;
    asm("mov.b64 %0, {%1, %2};" : "=l"(r) : "f"(lo), "f"(hi));
    return r;
}

// -------------------------------------------------------------------------
// Kernel 1: IoU pass. grid = (NBLK, NB), block = 256. Thread owns one anchor.
//   R12 structure (proven 69.8us); key store via uint2 (no shift/or) and
//   unroll 20 to halve residual loop overhead.
// -------------------------------------------------------------------------
__global__ __launch_bounds__(TPB) void k_main(const float* __restrict__ targets,
                                              const float* __restrict__ anchors) {
    __shared__ float4             s_box [NT];
    __shared__ float              s_area[NT];
    __shared__ unsigned long long s_key [8 * NT];   // [warp][t]

    const int tid  = threadIdx.x;
    const int wid  = tid >> 5;
    const int lane = tid & 31;
    const int b    = blockIdx.y;

    for (int t = tid; t < NT; t += TPB) {
        const float* tp = targets + ((size_t)b * NT + t) * 5;
        float x1 = tp[0], y1 = tp[1], x2 = tp[2], y2 = tp[3];
        s_box[t]  = make_float4(x1, y1, x2, y2);
        s_area[t] = __fmul_rn(__fsub_rn(x2, x1), __fsub_rn(y2, y1));
    }
    // REQUIRED: fully-OOB warps never store keys; their slots must be 0.
    for (int i = tid; i < 8 * NT; i += TPB) s_key[i] = 0ull;
    __syncthreads();

    const int  a       = blockIdx.x * TPB + tid;
    const bool valid   = (a < NA);
    const int  a_ld    = valid ? a : (NA - 1);   // OOB lanes dup last anchor's iou
    const int  warp_a0 = blockIdx.x * TPB + wid * 32;
    const bool w_store = (lane == 0) && (warp_a0 < NA);
    // REAL a (not clamped): OOB lanes get strictly smaller inv than the valid
    // lane holding the same iou, so they can never win the election.
    const unsigned inv_a = 0xFFFFFFFFu - (unsigned)a;

    // anchor point-form, replicating reference arithmetic exactly
    const float4 an = reinterpret_cast<const float4*>(anchors)[a_ld];
    const float hw  = __fmul_rn(an.z, 0.5f);
    const float hh  = __fmul_rn(an.w, 0.5f);
    const float ax1 = __fsub_rn(an.x, hw), ay1 = __fsub_rn(an.y, hh);
    const float ax2 = __fadd_rn(an.x, hw), ay2 = __fadd_rn(an.y, hh);
    const float areaA = __fmul_rn(__fsub_rn(ax2, ax1), __fsub_rn(ay2, ay1));

    const unsigned long long neg1 = pack2(-1.0f, -1.0f);

    float best_ov = -1.0f;
    int   best_t  = 0;
    unsigned long long* skw = &s_key[wid * NT];

#pragma unroll 20
    for (int t = 0; t < NT; ++t) {
        const float4 tb   = s_box[t];
        const float areaB = s_area[t];
        const float tlx = fmaxf(tb.x, ax1);
        const float tly = fmaxf(tb.y, ay1);
        const float brx = fminf(tb.z, ax2);
        const float bry = fminf(tb.w, ay2);

        // d = br - tl for both components in ONE packed fma (tl*(-1)+br),
        // exactly-rounded rn subtract per lane — bit-identical to __fsub_rn.
        unsigned long long tl2 = pack2(tlx, tly);
        unsigned long long br2 = pack2(brx, bry);
        unsigned long long d2;
        asm("fma.rn.f32x2 %0, %1, %2, %3;" : "=l"(d2) : "l"(tl2), "l"(neg1), "l"(br2));
        float dxr, dyr;
        asm("mov.b64 {%0, %1}, %2;" : "=f"(dxr), "=f"(dyr) : "l"(d2));

        const float dx  = fmaxf(dxr, 0.0f);
        const float dy  = fmaxf(dyr, 0.0f);
        const float inter = __fmul_rn(dx, dy);
        const float denom = __fsub_rn(__fadd_rn(areaB, areaA), inter);
        const float iou   = fdiv_rn_fast(inter, denom);

        // per-anchor argmax over t (strict > keeps first/lowest t)
        const bool gt = (iou > best_ov);
        best_ov = gt ? iou : best_ov;
        best_t  = gt ? t   : best_t;

        // per-target warp argmax: double REDUX (uniform result), lane-0 store
        const unsigned ib   = __float_as_uint(iou);
        const unsigned wmax = __reduce_max_sync(0xFFFFFFFFu, ib);
        const unsigned cand = (ib == wmax) ? inv_a : 0u;
        const unsigned wlow = __reduce_max_sync(0xFFFFFFFFu, cand);
        // little-endian: {lo=wlow, hi=wmax} == (wmax<<32)|wlow — no shift/or
        if (w_store)
            *reinterpret_cast<uint2*>(skw + t) = make_uint2(wlow, wmax);
    }

    if (valid) {
        g_gt_ov [(size_t)b * NA + a] = best_ov;
        g_gt_idx[(size_t)b * NA + a] = best_t;
        g_ovr   [(size_t)b * NA + a] = -1;            // cleared for k_merge scatter
    }

    __syncthreads();
    // merge 8 warps -> one key per t for this anchor tile
    if (tid < NT) {
        unsigned long long m = 0ull;
#pragma unroll
        for (int w = 0; w < 8; ++w) {
            unsigned long long v = s_key[w * NT + tid];
            m = (v > m) ? v : m;
        }
        g_part[((size_t)blockIdx.x * NB + b) * NT + tid] = m;
    }
}

// -------------------------------------------------------------------------
// Kernel 2: merge tiles + scatter override. 6400 threads, one per (b,t).
//   Last-t-wins scatter via atomicMax on t (== in-order scatter semantics).
// -------------------------------------------------------------------------
__global__ __launch_bounds__(TPB) void k_merge() {
    const int i = blockIdx.x * TPB + threadIdx.x;
    if (i >= NB * NT) return;
    const int b = i / NT;
    const int t = i - b * NT;

    unsigned long long m = 0ull;
#pragma unroll
    for (int p = 0; p < NBLK; ++p) {
        unsigned long long v = g_part[((size_t)p * NB + b) * NT + t];
        m = (v > m) ? v : m;
    }
    const int aidx = (int)(0xFFFFFFFFu - (unsigned)(m & 0xFFFFFFFFull));
    atomicMax(&g_ovr[(size_t)b * NA + aidx], t);
}

// -------------------------------------------------------------------------
// Kernel 3: finalize / encode. grid = (NBLK, NB), block = 256.
//   Output-only math: fast log/div are fine (1e-6 err vs 1e-3 tolerance);
//   all argmax/threshold-relevant values came from the exact pass.
// -------------------------------------------------------------------------
__global__ __launch_bounds__(TPB) void k_final(const float* __restrict__ targets,
                                               const float* __restrict__ anchors,
                                               float* __restrict__ out) {
    __shared__ float4 s_box[NT];
    __shared__ float  s_lab[NT];

    const int tid = threadIdx.x;
    const int b   = blockIdx.y;

    for (int t = tid; t < NT; t += TPB) {
        const float* tp = targets + ((size_t)b * NT + t) * 5;
        s_box[t] = make_float4(tp[0], tp[1], tp[2], tp[3]);
        s_lab[t] = tp[4];
    }
    __syncthreads();

    const int a = blockIdx.x * TPB + tid;
    if (a >= NA) return;

    int   gi = g_gt_idx[(size_t)b * NA + a];
    float ov = g_gt_ov [(size_t)b * NA + a];
    const int ovr = g_ovr[(size_t)b * NA + a];
    if (ovr >= 0) { gi = ovr; ov = 1.0f; }

    const float4 m   = s_box[gi];
    const float  lab = s_lab[gi];
    const float4 an  = reinterpret_cast<const float4*>(anchors)[a];

    const float cx = (m.x + m.z) * 0.5f;
    const float cy = (m.y + m.w) * 0.5f;
    const float w  = m.z - m.x;
    const float h  = m.w - m.y;

    const float lx = __fdividef(cx - an.x, 0.1f * an.z);
    const float ly = __fdividef(cy - an.y, 0.1f * an.w);
    const float lw = __logf(__fdividef(w, an.z)) * 5.0f;
    const float lh = __logf(__fdividef(h, an.w)) * 5.0f;

    const size_t base = (size_t)b * NA + a;
    reinterpret_cast<float4*>(out)[base] = make_float4(lx, ly, lw, lh);

    const float conf = (ov < 0.5f) ? 0.0f : (lab + 1.0f);
    out[(size_t)NB * NA * 4 + base] = conf;
}

// -------------------------------------------------------------------------
extern "C" void kernel_launch(void* const* d_in, const int* in_sizes, int n_in,
                              void* d_out, int out_size) {
    const float* targets = (const float*)d_in[0];   // [B, T, 5]
    const float* anchors = (const float*)d_in[1];   // [A, 4]
    float* out = (float*)d_out;                     // [B*A*4 loc][B*A conf]

    k_main <<<dim3(NBLK, NB), TPB>>>(targets, anchors);
    k_merge<<<(NB * NT + TPB - 1) / TPB, TPB>>>();
    k_final<<<dim3(NBLK, NB), TPB>>>(targets, anchors, out);
}